// round 9
// baseline (speedup 1.0000x reference)
#include <cuda_runtime.h>
#include <cuda_fp16.h>
#include <cstdint>
#include <cstddef>

// Problem constants
#define TOKENS 32768      // 8 * 4096
#define DIN    1024
#define RNK    64
#define NE     8
#define N72    72         // NE + RNK
#define DOUT   1024
#define KMID   512        // NE * RNK
#define SCALING 0.25f     // alpha / r = 16/64

// ---------------------------------------------------------------------------
// Scratch (device globals)
// ---------------------------------------------------------------------------
__device__ __half g_W72h[N72 * DIN];             // [72][1024] fp16
__device__ __half g_Wt[DOUT * KMID];             // [o][k]: Wt[o][e*64+r] = B[e][o][r]

// ---------------------------------------------------------------------------
// Helpers
// ---------------------------------------------------------------------------
__device__ __forceinline__ void mma16(float c[4], const unsigned a[4],
                                      unsigned b0, unsigned b1) {
    asm volatile(
        "mma.sync.aligned.m16n8k16.row.col.f32.f16.f16.f32 "
        "{%0,%1,%2,%3}, {%4,%5,%6,%7}, {%8,%9}, {%0,%1,%2,%3};\n"
        : "+f"(c[0]), "+f"(c[1]), "+f"(c[2]), "+f"(c[3])
        : "r"(a[0]), "r"(a[1]), "r"(a[2]), "r"(a[3]), "r"(b0), "r"(b1));
}

__device__ __forceinline__ void cp16(void* smem, const void* gmem) {
    unsigned saddr = (unsigned)__cvta_generic_to_shared(smem);
    asm volatile("cp.async.cg.shared.global [%0], [%1], 16;\n"
                 :: "r"(saddr), "l"(gmem));
}

__device__ __forceinline__ uint32_t smem_u32(const void* p) {
    return (uint32_t)__cvta_generic_to_shared(p);
}

__device__ __forceinline__ void ldsm4(unsigned& r0, unsigned& r1,
                                      unsigned& r2, unsigned& r3,
                                      uint32_t addr) {
    asm volatile("ldmatrix.sync.aligned.m8n8.x4.shared.b16 "
                 "{%0,%1,%2,%3}, [%4];"
                 : "=r"(r0), "=r"(r1), "=r"(r2), "=r"(r3) : "r"(addr));
}

// ---------------------------------------------------------------------------
// K0: prep weights (fp16)
// ---------------------------------------------------------------------------
__global__ void k0_prep(const float* __restrict__ route_w,
                        const float* __restrict__ A,
                        const float* __restrict__ B) {
    int idx = blockIdx.x * 256 + threadIdx.x;
    if (idx < N72 * DIN) {
        int n = idx / DIN, d = idx % DIN;
        float v = (n < NE) ? route_w[n * DIN + d] : A[(n - NE) * DIN + d];
        g_W72h[idx] = __float2half_rn(v);
    }
    int j = idx - N72 * DIN;
    if (j >= 0 && j < DOUT * KMID) {
        int o = j / KMID, k = j % KMID;
        int e = k >> 6, r = k & 63;
        g_Wt[j] = __float2half_rn(B[(e * DOUT + o) * RNK + r]);
    }
}

// ---------------------------------------------------------------------------
// KF: FUSED kernel. Per CTA (128 tokens, 256 threads):
//   Phase 1: C72 = X @ W72^T (fp16 mma) -> softmax -> outer -> D tile in SMEM
//   Phase 2: Y[128, 1024] = (D @ Wt^T) * SCALING, Wt streamed via cp.async,
//            A-fragments ldmatrix'd straight from the D smem tile.
// SMEM: D 128 x 520 halves (133120 B, stride 1040 B -> ldmatrix conflict-free)
//       + shared region 38912 B (phase1 Xs/Ws/Cs  ∪  phase2 Wt double buffer)
// ---------------------------------------------------------------------------
#define DP 520                               // D row stride in halves
#define D_BYTES (128 * DP * 2)               // 133120
#define SHREG_BYTES 38912                    // max(Cs, Xs+Ws, 2 Wt stages)
#define KF_SMEM (D_BYTES + SHREG_BYTES)      // 172032

__global__ __launch_bounds__(256, 1) void kf_fused(const float* __restrict__ X,
                                                   float* __restrict__ Y) {
    extern __shared__ char smraw[];
    __half* Dt = (__half*)smraw;                     // D tile
    char*   shreg = smraw + D_BYTES;                 // shared region

    int tid = threadIdx.x, warp = tid >> 5, lane = tid & 31;
    int m0 = blockIdx.x * 128;

    // ===================== Phase 1: router + compress =====================
    {
        unsigned* Xs = (unsigned*)shreg;             // [128][36] words
        unsigned* Ws = (unsigned*)shreg + 128 * 36;  // [72][36] words

        float acc[9][4] = {};
        float4 xr[8];
        uint4  wr[3];

        auto loadg = [&](int kt) {
            #pragma unroll
            for (int i = 0; i < 8; i++) {
                int idx = tid + i * 256;
                int r = idx >> 4, c4 = idx & 15;
                xr[i] = *(const float4*)(X + (size_t)(m0 + r) * DIN + kt + c4 * 4);
            }
            #pragma unroll
            for (int i = 0; i < 3; i++) {
                int idx = tid + i * 256;
                if (idx < 576) {
                    int r = idx >> 3, c = idx & 7;
                    wr[i] = *(const uint4*)((const char*)(g_W72h + r * DIN + kt) + c * 16);
                }
            }
        };

        loadg(0);

        for (int kt = 0; kt < 16; kt++) {
            #pragma unroll
            for (int i = 0; i < 8; i++) {
                int idx = tid + i * 256;
                int r = idx >> 4, c4 = idx & 15;
                __half2* dst = (__half2*)(Xs + r * 36 + c4 * 2);
                dst[0] = __floats2half2_rn(xr[i].x, xr[i].y);
                dst[1] = __floats2half2_rn(xr[i].z, xr[i].w);
            }
            #pragma unroll
            for (int i = 0; i < 3; i++) {
                int idx = tid + i * 256;
                if (idx < 576) {
                    int r = idx >> 3, c = idx & 7;
                    *(uint4*)(Ws + r * 36 + c * 4) = wr[i];
                }
            }
            __syncthreads();

            if (kt + 1 < 16) loadg((kt + 1) * 64);

            #pragma unroll
            for (int s = 0; s < 4; s++) {
                unsigned a[4];
                int ar = warp * 16 + (lane >> 2);
                int w = s * 8 + (lane & 3);
                a[0] = Xs[ar * 36 + w];
                a[1] = Xs[(ar + 8) * 36 + w];
                a[2] = Xs[ar * 36 + w + 4];
                a[3] = Xs[(ar + 8) * 36 + w + 4];
                #pragma unroll
                for (int j = 0; j < 9; j++) {
                    int br = j * 8 + (lane >> 2);
                    unsigned b0 = Ws[br * 36 + w];
                    unsigned b1 = Ws[br * 36 + w + 4];
                    mma16(acc[j], a, b0, b1);
                }
            }
            __syncthreads();
        }

        // stage C72 into smem: Cs[128][76]
        float* Cs = (float*)shreg;
        #pragma unroll
        for (int j = 0; j < 9; j++) {
            int col = j * 8 + 2 * (lane & 3);
            int row = warp * 16 + (lane >> 2);
            Cs[row * 76 + col]           = acc[j][0];
            Cs[row * 76 + col + 1]       = acc[j][1];
            Cs[(row + 8) * 76 + col]     = acc[j][2];
            Cs[(row + 8) * 76 + col + 1] = acc[j][3];
        }
        __syncthreads();

        // softmax + outer product -> D tile (fp16, smem)
        int grp = tid >> 3, g = tid & 7;
        #pragma unroll
        for (int tt = 0; tt < 4; tt++) {
            int lt = grp + tt * 32;
            const float* crow = Cs + lt * 76;
            float mx = crow[0];
            #pragma unroll
            for (int e = 1; e < 8; e++) mx = fmaxf(mx, crow[e]);
            float p[8]; float se = 0.f;
            #pragma unroll
            for (int e = 0; e < 8; e++) { p[e] = expf(crow[e] - mx); se += p[e]; }
            float inv = 1.f / se;
            __half* drow = Dt + lt * DP;
            #pragma unroll
            for (int e = 0; e < 8; e++) {
                float route = p[e] * inv;
                #pragma unroll
                for (int h = 0; h < 2; h++) {
                    int r = (g + h * 8) * 4;
                    float4 cv = *(const float4*)(crow + 8 + r);
                    __half2 h0 = __floats2half2_rn(route * cv.x, route * cv.y);
                    __half2 h1 = __floats2half2_rn(route * cv.z, route * cv.w);
                    *(__half2*)(drow + e * 64 + r)     = h0;
                    *(__half2*)(drow + e * 64 + r + 2) = h1;
                }
            }
        }
        __syncthreads();       // Cs dead; shared region now free for Wt ring
    }

    // ===================== Phase 2: GEMM2 over 8 n-chunks =================
    {
        // 8 warps as 2x4: wm in {0,1} rows, wn in {0..3} cols; warp tile 64x32
        int wm = warp >> 2, wn = warp & 3;

        unsigned* wt0 = (unsigned*)shreg;             // stage 0: [128][36] words
        unsigned* wt1 = (unsigned*)shreg + 128 * 36;  // stage 1
        uint32_t uW[2] = { smem_u32(wt0), smem_u32(wt1) };
        uint32_t uD = smem_u32(Dt);

        // ldmatrix lane-relative offsets
        int g4 = lane >> 3, lr = lane & 7;
        int rowSel = (g4 & 1) * 8 + lr;
        int wordSel = (g4 >> 1) * 4;
        uint32_t relA[4];
        #pragma unroll
        for (int mt = 0; mt < 4; mt++)
            relA[mt] = (uint32_t)(wm * 64 + mt * 16 + rowSel) * (DP * 2) + wordSel * 4;
        int browSel = (g4 >> 1) * 8 + lr;
        int bwordSel = (g4 & 1) * 4;
        uint32_t relB[2];
        #pragma unroll
        for (int np = 0; np < 2; np++)
            relB[np] = ((wn * 32 + np * 16 + browSel) * 36 + bwordSel) * 4;

        // prefetch flat tile f: n = f>>3, k = f&7; 128 Wt rows x 64 halves
        auto prefetch = [&](int f, int st) {
            int n = f >> 3, k = f & 7;
            unsigned* Bs = st ? wt1 : wt0;
            const __half* gB = g_Wt + (size_t)(n * 128) * KMID + k * 64;
            #pragma unroll
            for (int i = 0; i < 4; i++) {
                int j = tid + i * 256;
                int r = j >> 3, c = j & 7;
                cp16(Bs + r * 36 + c * 4, (const char*)(gB + (size_t)r * KMID) + c * 16);
            }
            asm volatile("cp.async.commit_group;\n" ::: "memory");
        };

        float acc[4][4][4] = {};

        prefetch(0, 0);

        for (int f = 0; f < 64; f++) {
            int st = f & 1;
            if (f + 1 < 64) {
                prefetch(f + 1, st ^ 1);
                asm volatile("cp.async.wait_group 1;\n" ::: "memory");
            } else {
                asm volatile("cp.async.wait_group 0;\n" ::: "memory");
            }
            __syncthreads();

            int k = f & 7;
            uint32_t aBase = uD + (uint32_t)k * 128;   // k*64 halves = 128 B
            #pragma unroll
            for (int s = 0; s < 4; s++) {
                unsigned a[4][4], b[2][4];
                #pragma unroll
                for (int mt = 0; mt < 4; mt++)
                    ldsm4(a[mt][0], a[mt][1], a[mt][2], a[mt][3],
                          aBase + relA[mt] + s * 32);
                #pragma unroll
                for (int np = 0; np < 2; np++)
                    ldsm4(b[np][0], b[np][1], b[np][2], b[np][3],
                          uW[st] + relB[np] + s * 32);
                #pragma unroll
                for (int mt = 0; mt < 4; mt++) {
                    #pragma unroll
                    for (int np = 0; np < 2; np++) {
                        mma16(acc[mt][np * 2],     a[mt], b[np][0], b[np][1]);
                        mma16(acc[mt][np * 2 + 1], a[mt], b[np][2], b[np][3]);
                    }
                }
            }
            __syncthreads();

            if (k == 7) {
                // epilogue for this n-chunk, then reset accumulators
                int n0 = (f >> 3) * 128;
                #pragma unroll
                for (int mt = 0; mt < 4; mt++) {
                    #pragma unroll
                    for (int nt = 0; nt < 4; nt++) {
                        int row = m0 + wm * 64 + mt * 16 + (lane >> 2);
                        int col = n0 + wn * 32 + nt * 8 + 2 * (lane & 3);
                        float2 v0 = make_float2(acc[mt][nt][0] * SCALING,
                                                acc[mt][nt][1] * SCALING);
                        float2 v1 = make_float2(acc[mt][nt][2] * SCALING,
                                                acc[mt][nt][3] * SCALING);
                        *(float2*)(Y + (size_t)row * DOUT + col)       = v0;
                        *(float2*)(Y + (size_t)(row + 8) * DOUT + col) = v1;
                        acc[mt][nt][0] = 0.f; acc[mt][nt][1] = 0.f;
                        acc[mt][nt][2] = 0.f; acc[mt][nt][3] = 0.f;
                    }
                }
            }
        }
    }
}

// ---------------------------------------------------------------------------
// Launch
// ---------------------------------------------------------------------------
extern "C" void kernel_launch(void* const* d_in, const int* in_sizes, int n_in,
                              void* d_out, int out_size) {
    (void)in_sizes; (void)n_in; (void)out_size;
    const float* x       = (const float*)d_in[0];
    const float* route_w = (const float*)d_in[1];
    const float* A       = (const float*)d_in[2];
    const float* B       = (const float*)d_in[3];
    float* y = (float*)d_out;

    cudaFuncSetAttribute(kf_fused, cudaFuncAttributeMaxDynamicSharedMemorySize,
                         KF_SMEM);

    int prep_elems = N72 * DIN + DOUT * KMID;
    k0_prep<<<(prep_elems + 255) / 256, 256>>>(route_w, A, B);
    kf_fused<<<TOKENS / 128, 256, KF_SMEM>>>(x, y);
}

// round 10
// speedup vs baseline: 1.2976x; 1.2976x over previous
#include <cuda_runtime.h>
#include <cuda_fp16.h>
#include <cstdint>
#include <cstddef>

// Problem constants
#define TOKENS 32768      // 8 * 4096
#define DIN    1024
#define RNK    64
#define NE     8
#define N72    72         // NE + RNK
#define DOUT   1024
#define KMID   512        // NE * RNK
#define SCALING 0.25f     // alpha / r = 16/64

#define NMB    256        // number of 128-token m-blocks
// ---------------------------------------------------------------------------
// Scratch (device globals)
// ---------------------------------------------------------------------------
__device__ __half g_W72h[N72 * DIN];             // [72][1024] fp16
__device__ __half g_Wt[DOUT * KMID];             // [o][k]: Wt[o][e*64+r] = B[e][o][r]
__device__ __half g_Dh[(size_t)TOKENS * KMID];   // 32 MiB: D[t][e*64+r] fp16
__device__ unsigned g_flag[NMB];                 // per-m-block ready flags

// ---------------------------------------------------------------------------
// Helpers
// ---------------------------------------------------------------------------
__device__ __forceinline__ void mma16(float c[4], const unsigned a[4],
                                      unsigned b0, unsigned b1) {
    asm volatile(
        "mma.sync.aligned.m16n8k16.row.col.f32.f16.f16.f32 "
        "{%0,%1,%2,%3}, {%4,%5,%6,%7}, {%8,%9}, {%0,%1,%2,%3};\n"
        : "+f"(c[0]), "+f"(c[1]), "+f"(c[2]), "+f"(c[3])
        : "r"(a[0]), "r"(a[1]), "r"(a[2]), "r"(a[3]), "r"(b0), "r"(b1));
}

__device__ __forceinline__ void cp16(void* smem, const void* gmem) {
    unsigned saddr = (unsigned)__cvta_generic_to_shared(smem);
    asm volatile("cp.async.cg.shared.global [%0], [%1], 16;\n"
                 :: "r"(saddr), "l"(gmem));
}

__device__ __forceinline__ uint32_t smem_u32(const void* p) {
    return (uint32_t)__cvta_generic_to_shared(p);
}

__device__ __forceinline__ void ldsm4(unsigned& r0, unsigned& r1,
                                      unsigned& r2, unsigned& r3,
                                      uint32_t addr) {
    asm volatile("ldmatrix.sync.aligned.m8n8.x4.shared.b16 "
                 "{%0,%1,%2,%3}, [%4];"
                 : "=r"(r0), "=r"(r1), "=r"(r2), "=r"(r3) : "r"(addr));
}

// ---------------------------------------------------------------------------
// K0: prep weights (fp16) + reset flags
// ---------------------------------------------------------------------------
__global__ void k0_prep(const float* __restrict__ route_w,
                        const float* __restrict__ A,
                        const float* __restrict__ B) {
    int idx = blockIdx.x * 256 + threadIdx.x;
    if (idx < NMB) g_flag[idx] = 0;
    if (idx < N72 * DIN) {
        int n = idx / DIN, d = idx % DIN;
        float v = (n < NE) ? route_w[n * DIN + d] : A[(n - NE) * DIN + d];
        g_W72h[idx] = __float2half_rn(v);
    }
    int j = idx - N72 * DIN;
    if (j >= 0 && j < DOUT * KMID) {
        int o = j / KMID, k = j % KMID;
        int e = k >> 6, r = k & 63;
        g_Wt[j] = __float2half_rn(B[(e * DOUT + o) * RNK + r]);
    }
}

// ---------------------------------------------------------------------------
// K_MAIN: producer/consumer fused grid.
//   bids [0, 256):      producer — router+compress -> softmax -> D (gmem) -> flag
//   bids [256, 2304):   consumer — GEMM2 tile (m = q>>3, n = q&7), spins on flag[m]
// 256 threads, <=2 CTAs/SM. Wave 1 holds bids 0..295 -> all producers resident
// before any consumer can starve them (consumers wait on low m first anyway).
// ---------------------------------------------------------------------------
#define BM 128
#define BN 128
#define NKT 8                               // 512 / 64
#define STG_W (2 * BM * 36)                 // A+B words per stage
#define KM_SMEM (2 * STG_W * 4)             // 73728 B (covers producer's 38912)

__global__ __launch_bounds__(256, 2) void k_main(const float* __restrict__ X,
                                                 float* __restrict__ Y) {
    extern __shared__ char smraw[];
    int tid = threadIdx.x, warp = tid >> 5, lane = tid & 31;
    int bid = blockIdx.x;

    if (bid < NMB) {
        // ===================== PRODUCER (k1 body) =====================
        int m0 = bid * 128;
        unsigned* Xs = (unsigned*)smraw;             // [128][36] words
        unsigned* Ws = (unsigned*)smraw + 128 * 36;  // [72][36] words

        float acc[9][4] = {};
        float4 xr[8];
        uint4  wr[3];

        auto loadg = [&](int kt) {
            #pragma unroll
            for (int i = 0; i < 8; i++) {
                int idx = tid + i * 256;
                int r = idx >> 4, c4 = idx & 15;
                xr[i] = *(const float4*)(X + (size_t)(m0 + r) * DIN + kt + c4 * 4);
            }
            #pragma unroll
            for (int i = 0; i < 3; i++) {
                int idx = tid + i * 256;
                if (idx < 576) {
                    int r = idx >> 3, c = idx & 7;
                    wr[i] = *(const uint4*)((const char*)(g_W72h + r * DIN + kt) + c * 16);
                }
            }
        };

        loadg(0);

        for (int kt = 0; kt < 16; kt++) {
            #pragma unroll
            for (int i = 0; i < 8; i++) {
                int idx = tid + i * 256;
                int r = idx >> 4, c4 = idx & 15;
                __half2* dst = (__half2*)(Xs + r * 36 + c4 * 2);
                dst[0] = __floats2half2_rn(xr[i].x, xr[i].y);
                dst[1] = __floats2half2_rn(xr[i].z, xr[i].w);
            }
            #pragma unroll
            for (int i = 0; i < 3; i++) {
                int idx = tid + i * 256;
                if (idx < 576) {
                    int r = idx >> 3, c = idx & 7;
                    *(uint4*)(Ws + r * 36 + c * 4) = wr[i];
                }
            }
            __syncthreads();

            if (kt + 1 < 16) loadg((kt + 1) * 64);

            #pragma unroll
            for (int s = 0; s < 4; s++) {
                unsigned a[4];
                int ar = warp * 16 + (lane >> 2);
                int w = s * 8 + (lane & 3);
                a[0] = Xs[ar * 36 + w];
                a[1] = Xs[(ar + 8) * 36 + w];
                a[2] = Xs[ar * 36 + w + 4];
                a[3] = Xs[(ar + 8) * 36 + w + 4];
                #pragma unroll
                for (int j = 0; j < 9; j++) {
                    int br = j * 8 + (lane >> 2);
                    unsigned b0 = Ws[br * 36 + w];
                    unsigned b1 = Ws[br * 36 + w + 4];
                    mma16(acc[j], a, b0, b1);
                }
            }
            __syncthreads();
        }

        // stage C72 into smem: Cs[128][76]
        float* Cs = (float*)smraw;
        #pragma unroll
        for (int j = 0; j < 9; j++) {
            int col = j * 8 + 2 * (lane & 3);
            int row = warp * 16 + (lane >> 2);
            Cs[row * 76 + col]           = acc[j][0];
            Cs[row * 76 + col + 1]       = acc[j][1];
            Cs[(row + 8) * 76 + col]     = acc[j][2];
            Cs[(row + 8) * 76 + col + 1] = acc[j][3];
        }
        __syncthreads();

        // softmax + outer product -> g_Dh
        int grp = tid >> 3, g = tid & 7;
        #pragma unroll
        for (int tt = 0; tt < 4; tt++) {
            int lt = grp + tt * 32;
            const float* crow = Cs + lt * 76;
            float mx = crow[0];
            #pragma unroll
            for (int e = 1; e < 8; e++) mx = fmaxf(mx, crow[e]);
            float p[8]; float se = 0.f;
            #pragma unroll
            for (int e = 0; e < 8; e++) { p[e] = expf(crow[e] - mx); se += p[e]; }
            float inv = 1.f / se;
            __half* drow = g_Dh + (size_t)(m0 + lt) * KMID;
            #pragma unroll
            for (int e = 0; e < 8; e++) {
                float route = p[e] * inv;
                #pragma unroll
                for (int h = 0; h < 2; h++) {
                    int r = (g + h * 8) * 4;
                    float4 cv = *(const float4*)(crow + 8 + r);
                    __half2 h0 = __floats2half2_rn(route * cv.x, route * cv.y);
                    __half2 h1 = __floats2half2_rn(route * cv.z, route * cv.w);
                    *(__half2*)(drow + e * 64 + r)     = h0;
                    *(__half2*)(drow + e * 64 + r + 2) = h1;
                }
            }
        }

        // publish: all stores globally visible, then release flag
        __threadfence();
        __syncthreads();
        if (tid == 0) {
            asm volatile("st.release.gpu.global.u32 [%0], %1;"
                         :: "l"(&g_flag[bid]), "r"(1u) : "memory");
        }
        return;
    }

    // ===================== CONSUMER (GEMM2 tile) =====================
    {
        int q = bid - NMB;
        int mb = q >> 3;                 // m-block index (low m first)
        int nb = q & 7;
        int m0 = mb * BM, n0 = nb * BN;

        // spin until producer mb done
        if (tid == 0) {
            unsigned v = 0;
            while (true) {
                asm volatile("ld.acquire.gpu.global.u32 %0, [%1];"
                             : "=r"(v) : "l"(&g_flag[mb]) : "memory");
                if (v) break;
                __nanosleep(200);
            }
        }
        __syncthreads();

        unsigned* sh = (unsigned*)smraw;
        int wm = warp >> 2, wn = warp & 3;   // 2x4 warps, warp tile 64x32

        float acc[4][4][4] = {};

        unsigned* stA[2] = { sh, sh + STG_W };
        unsigned* stB[2] = { sh + BM * 36, sh + STG_W + BM * 36 };

        int g4 = lane >> 3, lr = lane & 7;
        uint32_t relA[4], relB[2];
        {
            int rowSel = (g4 & 1) * 8 + lr;
            int wordSel = (g4 >> 1) * 4;
            #pragma unroll
            for (int mt = 0; mt < 4; mt++)
                relA[mt] = ((wm * 64 + mt * 16 + rowSel) * 36 + wordSel) * 4;
            int browSel = (g4 >> 1) * 8 + lr;
            int bwordSel = (g4 & 1) * 4;
            #pragma unroll
            for (int np = 0; np < 2; np++)
                relB[np] = ((wn * 32 + np * 16 + browSel) * 36 + bwordSel) * 4;
        }
        uint32_t uA[2] = { smem_u32(stA[0]), smem_u32(stA[1]) };
        uint32_t uB[2] = { smem_u32(stB[0]), smem_u32(stB[1]) };

        auto prefetch = [&](int st, int kt) {
            unsigned* As = stA[st];
            unsigned* Bs = stB[st];
            const __half* gA = g_Dh + (size_t)m0 * KMID + kt * 64;
            const __half* gB = g_Wt + (size_t)n0 * KMID + kt * 64;
            #pragma unroll
            for (int i = 0; i < 4; i++) {
                int j = tid + i * 256;
                int r = j >> 3, c = j & 7;
                cp16(As + r * 36 + c * 4, (const char*)(gA + (size_t)r * KMID) + c * 16);
            }
            #pragma unroll
            for (int i = 0; i < 4; i++) {
                int j = tid + i * 256;
                int r = j >> 3, c = j & 7;
                cp16(Bs + r * 36 + c * 4, (const char*)(gB + (size_t)r * KMID) + c * 16);
            }
            asm volatile("cp.async.commit_group;\n" ::: "memory");
        };

        prefetch(0, 0);

        for (int kt = 0; kt < NKT; kt++) {
            int st = kt & 1;
            if (kt + 1 < NKT) {
                prefetch(st ^ 1, kt + 1);
                asm volatile("cp.async.wait_group 1;\n" ::: "memory");
            } else {
                asm volatile("cp.async.wait_group 0;\n" ::: "memory");
            }
            __syncthreads();

            #pragma unroll
            for (int s = 0; s < 4; s++) {
                unsigned a[4][4], b[2][4];
                #pragma unroll
                for (int mt = 0; mt < 4; mt++)
                    ldsm4(a[mt][0], a[mt][1], a[mt][2], a[mt][3],
                          uA[st] + relA[mt] + s * 32);
                #pragma unroll
                for (int np = 0; np < 2; np++)
                    ldsm4(b[np][0], b[np][1], b[np][2], b[np][3],
                          uB[st] + relB[np] + s * 32);
                #pragma unroll
                for (int mt = 0; mt < 4; mt++) {
                    #pragma unroll
                    for (int np = 0; np < 2; np++) {
                        mma16(acc[mt][np * 2],     a[mt], b[np][0], b[np][1]);
                        mma16(acc[mt][np * 2 + 1], a[mt], b[np][2], b[np][3]);
                    }
                }
            }
            __syncthreads();
        }

        // epilogue
        #pragma unroll
        for (int mt = 0; mt < 4; mt++) {
            #pragma unroll
            for (int nt = 0; nt < 4; nt++) {
                int row = m0 + wm * 64 + mt * 16 + (lane >> 2);
                int col = n0 + wn * 32 + nt * 8 + 2 * (lane & 3);
                float2 v0 = make_float2(acc[mt][nt][0] * SCALING,
                                        acc[mt][nt][1] * SCALING);
                float2 v1 = make_float2(acc[mt][nt][2] * SCALING,
                                        acc[mt][nt][3] * SCALING);
                *(float2*)(Y + (size_t)row * DOUT + col)       = v0;
                *(float2*)(Y + (size_t)(row + 8) * DOUT + col) = v1;
            }
        }
    }
}

// ---------------------------------------------------------------------------
// Launch
// ---------------------------------------------------------------------------
extern "C" void kernel_launch(void* const* d_in, const int* in_sizes, int n_in,
                              void* d_out, int out_size) {
    (void)in_sizes; (void)n_in; (void)out_size;
    const float* x       = (const float*)d_in[0];
    const float* route_w = (const float*)d_in[1];
    const float* A       = (const float*)d_in[2];
    const float* B       = (const float*)d_in[3];
    float* y = (float*)d_out;

    cudaFuncSetAttribute(k_main, cudaFuncAttributeMaxDynamicSharedMemorySize,
                         KM_SMEM);

    int prep_elems = N72 * DIN + DOUT * KMID;
    k0_prep<<<(prep_elems + 255) / 256, 256>>>(route_w, A, B);
    k_main<<<NMB + NMB * 8, 256, KM_SMEM>>>(x, y);
}